// round 2
// baseline (speedup 1.0000x reference)
#include <cuda_runtime.h>
#include <math.h>

#define B_ 4
#define C_ 128
#define H_ 8
#define DH_ 16
#define F_ 4096
#define NR_ 127
#define NS_ 16      // key-split chunks
#define CK_ 256     // keys per chunk
#define SMAX_ 64

// ----------------------------- scratch ------------------------------------
__device__ float g_Q[B_*H_*F_*DH_];                 // (b,h,n,d) 8 MB
__device__ float g_K[B_*H_*F_*DH_];
__device__ float g_V[B_*H_*F_*DH_];
__device__ float g_M[2][B_*H_*NS_*SMAX_];
__device__ float g_L[2][B_*H_*NS_*SMAX_];
__device__ float g_O[2][B_*H_*NS_*SMAX_*DH_];
__device__ float g_va[B_*C_];                       // Wv0 @ anchor
__device__ float g_k1[B_*H_*DH_];                   // normalized Wk1 @ anchor

// --------------------- prologue: Q/K/V = W @ x -----------------------------
// grid (F/32, 3, B), block 256 = 32 cols x 8 heads
__global__ void proj_kernel(const float* __restrict__ x,
                            const float* __restrict__ Wq,
                            const float* __restrict__ Wk,
                            const float* __restrict__ Wv) {
    __shared__ float WsT[64][132];
    const float* W   = (blockIdx.y == 0) ? Wq  : (blockIdx.y == 1 ? Wk  : Wv);
    float*       out = (blockIdx.y == 0) ? g_Q : (blockIdx.y == 1 ? g_K : g_V);
    const int b  = blockIdx.z;
    const int t  = threadIdx.x;
    const int tx = t & 31;
    const int ty = t >> 5;
    const int n  = blockIdx.x * 32 + tx;

    float acc[16];
#pragma unroll
    for (int i = 0; i < 16; i++) acc[i] = 0.f;

    for (int half = 0; half < 2; half++) {
        __syncthreads();
        for (int idx = t; idx < 64 * 128; idx += 256) {
            int co = idx >> 6, c = idx & 63;
            WsT[c][co] = W[co * 128 + half * 64 + c];
        }
        __syncthreads();
#pragma unroll 4
        for (int c = 0; c < 64; c++) {
            float xv = x[((size_t)(b * 128 + half * 64 + c)) * 4096 + n];
            const float4* wr = (const float4*)&WsT[c][ty * 16];
            float4 w0 = wr[0], w1 = wr[1], w2 = wr[2], w3 = wr[3];
            acc[0]  += w0.x * xv;  acc[1]  += w0.y * xv;
            acc[2]  += w0.z * xv;  acc[3]  += w0.w * xv;
            acc[4]  += w1.x * xv;  acc[5]  += w1.y * xv;
            acc[6]  += w1.z * xv;  acc[7]  += w1.w * xv;
            acc[8]  += w2.x * xv;  acc[9]  += w2.y * xv;
            acc[10] += w2.z * xv;  acc[11] += w2.w * xv;
            acc[12] += w3.x * xv;  acc[13] += w3.y * xv;
            acc[14] += w3.z * xv;  acc[15] += w3.w * xv;
        }
    }
    float4* dst = (float4*)&out[(((size_t)b * 8 + ty) * 4096 + n) * 16];
    dst[0] = make_float4(acc[0],  acc[1],  acc[2],  acc[3]);
    dst[1] = make_float4(acc[4],  acc[5],  acc[6],  acc[7]);
    dst[2] = make_float4(acc[8],  acc[9],  acc[10], acc[11]);
    dst[3] = make_float4(acc[12], acc[13], acc[14], acc[15]);
}

// ----------------- per-ring attention partial + lazy patch -----------------
struct PatchSm {
    float Wk[16][129];
    float Wv[16][129];
    float fc[5][129];
};
struct AttnSm {
    float4 K4[CK_][4];
    float4 V4[CK_][4];
    float  q[SMAX_][16];
};
union SmU { PatchSm p; AttnSm a; };

// grid (NS_, H_, B_), block 64
__global__ void attn_partial(int r,
                             const float* __restrict__ x,
                             const float* __restrict__ Wk0,
                             const float* __restrict__ Wv0,
                             float* __restrict__ feats_out) {
    __shared__ SmU sm;
    const int cs = blockIdx.x, h = blockIdx.y, b = blockIdx.z;
    const int t = threadIdx.x;
    const int lo = max(0, r - 63), hi = min(r, 63), s = hi - lo + 1;
    const int par  = r & 1;
    const int par1 = par ^ 1;

    // ---- phase 1: combine ring r-1 partials for cols in this chunk; patch K/V
    if (r > 0) {
        const int rm  = r - 1;
        const int lo1 = max(0, rm - 63), hi1 = min(rm, 63);
        int a = cs * 256 - rm;
        int imin = (a <= 0) ? lo1 : (a + 62) / 63;
        if (imin < lo1) imin = lo1;
        int imax = (cs * 256 + 255 - rm) / 63;
        if (imax > hi1) imax = hi1;
        const int np = imax - imin + 1;
        if (np > 0) {
            // load head-h rows of Wk0/Wv0
            for (int idx = t; idx < 16 * 128; idx += 64) {
                int row = idx >> 7, c = idx & 127;
                sm.p.Wk[row][c] = Wk0[(h * 16 + row) * 128 + c];
                sm.p.Wv[row][c] = Wv0[(h * 16 + row) * 128 + c];
            }
            // combine partials -> feats column values
            for (int idx = t; idx < np * 128; idx += 64) {
                int ci = idx >> 7, c = idx & 127;
                int hh = c >> 4, d = c & 15;
                int i  = imin + ci;
                int qi = i - lo1;
                int col = 63 * i + rm;
                int base = ((b * 8 + hh) * 16) * 64 + qi;
                float M = -1e30f, L = 0.f, O = 0.f;
#pragma unroll 4
                for (int ch = 0; ch < 16; ch++) {
                    int pidx = base + ch * 64;
                    float mc = g_M[par1][pidx];
                    float lc = g_L[par1][pidx];
                    float oc = g_O[par1][(size_t)pidx * 16 + d];
                    float nM = fmaxf(M, mc);
                    float e0 = __expf(M - nM), e1 = __expf(mc - nM);
                    L = L * e0 + lc * e1;
                    O = O * e0 + oc * e1;
                    M = nM;
                }
                float f = x[((size_t)(b * 128 + c)) * 4096 + col] + O / L;
                sm.p.fc[ci][c] = f;
                if (h == 0)
                    feats_out[((size_t)(b * 128 + c)) * 4096 + col] = f;
            }
            __syncthreads();
            // K/V patch for this head
            for (int w = t; w < np * 32; w += 64) {
                int which = w / (np * 16);          // 0->K, 1->V
                int m2 = w % (np * 16);
                int ci = m2 >> 4, row = m2 & 15;
                float accp = 0.f;
                if (which == 0) {
#pragma unroll 8
                    for (int c = 0; c < 128; c++) accp += sm.p.Wk[row][c] * sm.p.fc[ci][c];
                } else {
#pragma unroll 8
                    for (int c = 0; c < 128; c++) accp += sm.p.Wv[row][c] * sm.p.fc[ci][c];
                }
                int col = 63 * (imin + ci) + rm;
                float* dst = which ? g_V : g_K;
                dst[(((size_t)b * 8 + h) * 4096 + col) * 16 + row] = accp;
            }
        }
        __syncthreads();
    }

    // ---- phase 2: stage q, K-chunk, V-chunk into smem ----
    for (int idx = t; idx < s * 16; idx += 64) {
        int i = idx >> 4, d = idx & 15;
        int col = 63 * (lo + i) + r;
        sm.a.q[i][d] = g_Q[(((size_t)b * 8 + h) * 4096 + col) * 16 + d];
    }
    {
        const float4* K4 = (const float4*)&g_K[(((size_t)b * 8 + h) * 4096 + cs * CK_) * 16];
        const float4* V4 = (const float4*)&g_V[(((size_t)b * 8 + h) * 4096 + cs * CK_) * 16];
        float4* Kd = &sm.a.K4[0][0];
        float4* Vd = &sm.a.V4[0][0];
        for (int idx = t; idx < CK_ * 4; idx += 64) { Kd[idx] = K4[idx]; Vd[idx] = V4[idx]; }
    }
    __syncthreads();

    // ---- phase 3: online-softmax partial over this chunk ----
    if (t < s) {
        float q[16];
#pragma unroll
        for (int d = 0; d < 16; d++) q[d] = sm.a.q[t][d] * 0.25f;
        float m = -1e30f, l = 0.f;
        float o[16];
#pragma unroll
        for (int d = 0; d < 16; d++) o[d] = 0.f;

#pragma unroll 2
        for (int j = 0; j < CK_; j++) {
            float4 k0 = sm.a.K4[j][0], k1 = sm.a.K4[j][1];
            float4 k2 = sm.a.K4[j][2], k3 = sm.a.K4[j][3];
            float s0 = q[0]*k0.x + q[4]*k1.x + q[8]*k2.x  + q[12]*k3.x;
            float s1 = q[1]*k0.y + q[5]*k1.y + q[9]*k2.y  + q[13]*k3.y;
            float s2 = q[2]*k0.z + q[6]*k1.z + q[10]*k2.z + q[14]*k3.z;
            float s3 = q[3]*k0.w + q[7]*k1.w + q[11]*k2.w + q[15]*k3.w;
            float sc = (s0 + s1) + (s2 + s3);
            float nm = fmaxf(m, sc);
            float corr = __expf(m - nm);
            float p = __expf(sc - nm);
            l = l * corr + p;
            float4 v0 = sm.a.V4[j][0], v1 = sm.a.V4[j][1];
            float4 v2 = sm.a.V4[j][2], v3 = sm.a.V4[j][3];
            o[0]  = o[0]*corr  + p*v0.x;  o[1]  = o[1]*corr  + p*v0.y;
            o[2]  = o[2]*corr  + p*v0.z;  o[3]  = o[3]*corr  + p*v0.w;
            o[4]  = o[4]*corr  + p*v1.x;  o[5]  = o[5]*corr  + p*v1.y;
            o[6]  = o[6]*corr  + p*v1.z;  o[7]  = o[7]*corr  + p*v1.w;
            o[8]  = o[8]*corr  + p*v2.x;  o[9]  = o[9]*corr  + p*v2.y;
            o[10] = o[10]*corr + p*v2.z;  o[11] = o[11]*corr + p*v2.w;
            o[12] = o[12]*corr + p*v3.x;  o[13] = o[13]*corr + p*v3.y;
            o[14] = o[14]*corr + p*v3.z;  o[15] = o[15]*corr + p*v3.w;
            m = nm;
        }
        int pidx = ((b * 8 + h) * 16 + cs) * 64 + t;
        g_M[par][pidx] = m;
        g_L[par][pidx] = l;
#pragma unroll
        for (int d = 0; d < 16; d++) g_O[par][(size_t)pidx * 16 + d] = o[d];
    }
}

// ---------------- final combine for ring 126 -------------------------------
// grid (s, B), block 128
__global__ void combine_write(int r, const float* __restrict__ x,
                              float* __restrict__ feats_out) {
    const int b = blockIdx.y, qi = blockIdx.x, c = threadIdx.x;
    const int lo = max(0, r - 63);
    const int col = 63 * (lo + qi) + r;
    const int par = r & 1;
    const int hh = c >> 4, d = c & 15;
    int base = ((b * 8 + hh) * 16) * 64 + qi;
    float M = -1e30f, L = 0.f, O = 0.f;
#pragma unroll 4
    for (int ch = 0; ch < 16; ch++) {
        int pidx = base + ch * 64;
        float mc = g_M[par][pidx];
        float lc = g_L[par][pidx];
        float oc = g_O[par][(size_t)pidx * 16 + d];
        float nM = fmaxf(M, mc);
        float e0 = __expf(M - nM), e1 = __expf(mc - nM);
        L = L * e0 + lc * e1;
        O = O * e0 + oc * e1;
        M = nM;
    }
    feats_out[((size_t)(b * 128 + c)) * 4096 + col] =
        x[((size_t)(b * 128 + c)) * 4096 + col] + O / L;
}

// ---------------- epilogue 1: va = Wv0@anchor, k1 = normed Wk1@anchor ------
// grid B, block 128
__global__ void epi1_kernel(const float* __restrict__ Wv0,
                            const float* __restrict__ Wk1,
                            const float* __restrict__ feats_out) {
    __shared__ float anc[128];
    __shared__ float k1raw[128];
    __shared__ float hs[8];
    const int b = blockIdx.x, t = threadIdx.x;
    anc[t] = feats_out[((size_t)(b * 128 + t)) * 4096 + 0];
    __syncthreads();
    float av = 0.f, kv = 0.f;
#pragma unroll 8
    for (int c = 0; c < 128; c++) {
        av += Wv0[t * 128 + c] * anc[c];
        kv += Wk1[t * 128 + c] * anc[c];
    }
    g_va[b * 128 + t] = av;
    k1raw[t] = kv;
    __syncthreads();
    if (t < 8) {
        float ss = 0.f;
#pragma unroll
        for (int d = 0; d < 16; d++) { float v = k1raw[t * 16 + d]; ss += v * v; }
        hs[t] = rsqrtf(ss + 1e-8f);
    }
    __syncthreads();
    g_k1[(b * 8 + (t >> 4)) * 16 + (t & 15)] = k1raw[t] * hs[t >> 4];
}

// ---------------- epilogue 2: final scores ---------------------------------
// grid (F/32, B), block 256 = 32 cols x 8 heads
__global__ void epi2_kernel(const float* __restrict__ x,
                            const float* __restrict__ Wq1,
                            float* __restrict__ scores_out) {
    __shared__ float WsT[64][132];
    __shared__ float sva[128];
    __shared__ float sred[8][32];
    const int b  = blockIdx.y;
    const int t  = threadIdx.x;
    const int tx = t & 31;
    const int ty = t >> 5;
    const int n  = blockIdx.x * 32 + tx;

    if (t < 128) sva[t] = g_va[b * 128 + t];

    float acc[16];
#pragma unroll
    for (int i = 0; i < 16; i++) acc[i] = 0.f;

    for (int half = 0; half < 2; half++) {
        __syncthreads();
        for (int idx = t; idx < 64 * 128; idx += 256) {
            int co = idx >> 6, c = idx & 63;
            WsT[c][co] = Wq1[co * 128 + half * 64 + c];
        }
        __syncthreads();
#pragma unroll 4
        for (int c = 0; c < 64; c++) {
            float qx = x[((size_t)(b * 128 + half * 64 + c)) * 4096 + n] + sva[half * 64 + c];
            const float4* wr = (const float4*)&WsT[c][ty * 16];
            float4 w0 = wr[0], w1 = wr[1], w2 = wr[2], w3 = wr[3];
            acc[0]  += w0.x * qx;  acc[1]  += w0.y * qx;
            acc[2]  += w0.z * qx;  acc[3]  += w0.w * qx;
            acc[4]  += w1.x * qx;  acc[5]  += w1.y * qx;
            acc[6]  += w1.z * qx;  acc[7]  += w1.w * qx;
            acc[8]  += w2.x * qx;  acc[9]  += w2.y * qx;
            acc[10] += w2.z * qx;  acc[11] += w2.w * qx;
            acc[12] += w3.x * qx;  acc[13] += w3.y * qx;
            acc[14] += w3.z * qx;  acc[15] += w3.w * qx;
        }
    }
    float qq = 0.f, dot = 0.f;
#pragma unroll
    for (int d = 0; d < 16; d++) {
        qq  += acc[d] * acc[d];
        dot += acc[d] * g_k1[(b * 8 + ty) * 16 + d];
    }
    float m = dot * rsqrtf(qq + 1e-8f);
    sred[ty][tx] = (m + 1.0f) * 0.5f;
    __syncthreads();
    if (ty == 0) {
        float sum = 0.f;
#pragma unroll
        for (int hh = 0; hh < 8; hh++) sum += sred[hh][tx];
        scores_out[(size_t)b * 4096 + n] = sum * 0.125f;
    }
}

// ---------------------------------------------------------------------------
extern "C" void kernel_launch(void* const* d_in, const int* in_sizes, int n_in,
                              void* d_out, int out_size) {
    const float* x   = (const float*)d_in[0];
    const float* Wq0 = (const float*)d_in[1];
    const float* Wk0 = (const float*)d_in[2];
    const float* Wv0 = (const float*)d_in[3];
    const float* Wq1 = (const float*)d_in[4];
    const float* Wk1 = (const float*)d_in[5];
    float* feats_out  = (float*)d_out;
    float* scores_out = feats_out + (size_t)B_ * C_ * F_;

    proj_kernel<<<dim3(128, 3, B_), 256>>>(x, Wq0, Wk0, Wv0);

    for (int r = 0; r < NR_; r++) {
        attn_partial<<<dim3(NS_, H_, B_), 64>>>(r, x, Wk0, Wv0, feats_out);
    }
    combine_write<<<dim3(1, B_), 128>>>(126, x, feats_out);

    epi1_kernel<<<B_, 128>>>(Wv0, Wk1, feats_out);
    epi2_kernel<<<dim3(128, B_), 256>>>(x, Wq1, scores_out);
}

// round 3
// speedup vs baseline: 1.7215x; 1.7215x over previous
#include <cuda_runtime.h>
#include <math.h>

#define B_ 4
#define C_ 128
#define H_ 8
#define DH_ 16
#define F_ 4096
#define NR_ 127
#define NS_ 16      // key-split chunks
#define CK_ 256     // keys per chunk
#define SUB_ 4      // sub-chunks per CTA
#define KSUB_ 64    // keys per sub-chunk
#define SMAX_ 64

// ----------------------------- scratch ------------------------------------
__device__ float g_Q[B_*H_*F_*DH_];                 // (b,h,n,d) 8 MB
__device__ float g_K[B_*H_*F_*DH_];
__device__ float g_V[B_*H_*F_*DH_];
__device__ float g_M[2][B_*H_*NS_*SMAX_];
__device__ float g_L[2][B_*H_*NS_*SMAX_];
__device__ float g_O[2][B_*H_*NS_*SMAX_*DH_];
__device__ float g_va[B_*C_];                       // Wv0 @ anchor
__device__ float g_k1[B_*H_*DH_];                   // normalized Wk1 @ anchor

// --------------------- prologue: Q/K/V = W @ x -----------------------------
// grid (F/32, 3, B), block 256 = 32 cols x 8 heads
__global__ void proj_kernel(const float* __restrict__ x,
                            const float* __restrict__ Wq,
                            const float* __restrict__ Wk,
                            const float* __restrict__ Wv) {
    __shared__ float WsT[64][132];
    const float* W   = (blockIdx.y == 0) ? Wq  : (blockIdx.y == 1 ? Wk  : Wv);
    float*       out = (blockIdx.y == 0) ? g_Q : (blockIdx.y == 1 ? g_K : g_V);
    const int b  = blockIdx.z;
    const int t  = threadIdx.x;
    const int tx = t & 31;
    const int ty = t >> 5;
    const int n  = blockIdx.x * 32 + tx;

    float acc[16];
#pragma unroll
    for (int i = 0; i < 16; i++) acc[i] = 0.f;

    for (int half = 0; half < 2; half++) {
        __syncthreads();
        for (int idx = t; idx < 64 * 128; idx += 256) {
            int co = idx >> 6, c = idx & 63;
            WsT[c][co] = W[co * 128 + half * 64 + c];
        }
        __syncthreads();
#pragma unroll 4
        for (int c = 0; c < 64; c++) {
            float xv = x[((size_t)(b * 128 + half * 64 + c)) * 4096 + n];
            const float4* wr = (const float4*)&WsT[c][ty * 16];
            float4 w0 = wr[0], w1 = wr[1], w2 = wr[2], w3 = wr[3];
            acc[0]  += w0.x * xv;  acc[1]  += w0.y * xv;
            acc[2]  += w0.z * xv;  acc[3]  += w0.w * xv;
            acc[4]  += w1.x * xv;  acc[5]  += w1.y * xv;
            acc[6]  += w1.z * xv;  acc[7]  += w1.w * xv;
            acc[8]  += w2.x * xv;  acc[9]  += w2.y * xv;
            acc[10] += w2.z * xv;  acc[11] += w2.w * xv;
            acc[12] += w3.x * xv;  acc[13] += w3.y * xv;
            acc[14] += w3.z * xv;  acc[15] += w3.w * xv;
        }
    }
    float4* dst = (float4*)&out[(((size_t)b * 8 + ty) * 4096 + n) * 16];
    dst[0] = make_float4(acc[0],  acc[1],  acc[2],  acc[3]);
    dst[1] = make_float4(acc[4],  acc[5],  acc[6],  acc[7]);
    dst[2] = make_float4(acc[8],  acc[9],  acc[10], acc[11]);
    dst[3] = make_float4(acc[12], acc[13], acc[14], acc[15]);
}

// ----------------- per-ring attention partial + lazy patch -----------------
struct PatchSm {
    float Wk[16][129];
    float Wv[16][129];
    float fc[5][129];
};
struct AttnSm {
    float4 K4[CK_][4];      // 16 KB  (merge arrays alias this region)
    float4 V4[CK_][4];      // 16 KB
    float  q[SMAX_][16];    // 4 KB
};
union SmU { PatchSm p; AttnSm a; };

// merge scratch aliased over K4/V4 (32 KB available, uses ~19.7 KB)
struct MergeSm {
    float M[SMAX_][SUB_];
    float L[SMAX_][SUB_];
    float O[SMAX_][SUB_ * 17 + 1];   // padded: q-stride 69 floats (coprime w/ 32)
};

// grid (NS_, H_, B_), block 256
__global__ void __launch_bounds__(256, 4)
attn_partial(int r,
             const float* __restrict__ x,
             const float* __restrict__ Wk0,
             const float* __restrict__ Wv0,
             float* __restrict__ feats_out) {
    __shared__ SmU sm;
    const int cs = blockIdx.x, h = blockIdx.y, b = blockIdx.z;
    const int t = threadIdx.x;
    const int lo = max(0, r - 63), hi = min(r, 63), s = hi - lo + 1;
    const int par  = r & 1;
    const int par1 = par ^ 1;

    // ---- phase 1: combine ring r-1 partials for cols in this chunk; patch K/V
    if (r > 0) {
        const int rm  = r - 1;
        const int lo1 = max(0, rm - 63), hi1 = min(rm, 63);
        int a = cs * 256 - rm;
        int imin = (a <= 0) ? lo1 : (a + 62) / 63;
        if (imin < lo1) imin = lo1;
        int imax = (cs * 256 + 255 - rm) / 63;
        if (imax > hi1) imax = hi1;
        const int np = imax - imin + 1;
        if (np > 0) {
            for (int idx = t; idx < 16 * 128; idx += 256) {
                int row = idx >> 7, c = idx & 127;
                sm.p.Wk[row][c] = Wk0[(h * 16 + row) * 128 + c];
                sm.p.Wv[row][c] = Wv0[(h * 16 + row) * 128 + c];
            }
            for (int idx = t; idx < np * 128; idx += 256) {
                int ci = idx >> 7, c = idx & 127;
                int hh = c >> 4, d = c & 15;
                int i  = imin + ci;
                int qi = i - lo1;
                int col = 63 * i + rm;
                int base = ((b * 8 + hh) * 16) * 64 + qi;
                float M = -1e30f, L = 0.f, O = 0.f;
#pragma unroll 4
                for (int ch = 0; ch < 16; ch++) {
                    int pidx = base + ch * 64;
                    float mc = g_M[par1][pidx];
                    float lc = g_L[par1][pidx];
                    float oc = g_O[par1][(size_t)pidx * 16 + d];
                    float nM = fmaxf(M, mc);
                    float e0 = __expf(M - nM), e1 = __expf(mc - nM);
                    L = L * e0 + lc * e1;
                    O = O * e0 + oc * e1;
                    M = nM;
                }
                float f = x[((size_t)(b * 128 + c)) * 4096 + col] + O / L;
                sm.p.fc[ci][c] = f;
                if (h == 0)
                    feats_out[((size_t)(b * 128 + c)) * 4096 + col] = f;
            }
            __syncthreads();
            for (int w = t; w < np * 32; w += 256) {
                int which = w / (np * 16);          // 0->K, 1->V
                int m2 = w % (np * 16);
                int ci = m2 >> 4, row = m2 & 15;
                float accp = 0.f;
                if (which == 0) {
#pragma unroll 8
                    for (int c = 0; c < 128; c++) accp += sm.p.Wk[row][c] * sm.p.fc[ci][c];
                } else {
#pragma unroll 8
                    for (int c = 0; c < 128; c++) accp += sm.p.Wv[row][c] * sm.p.fc[ci][c];
                }
                int col = 63 * (imin + ci) + rm;
                float* dst = which ? g_V : g_K;
                dst[(((size_t)b * 8 + h) * 4096 + col) * 16 + row] = accp;
            }
        }
        __syncthreads();
    }

    // ---- phase 2: stage q, K-chunk, V-chunk into smem ----
    for (int idx = t; idx < s * 16; idx += 256) {
        int i = idx >> 4, d = idx & 15;
        int col = 63 * (lo + i) + r;
        sm.a.q[i][d] = g_Q[(((size_t)b * 8 + h) * 4096 + col) * 16 + d];
    }
    {
        const float4* K4 = (const float4*)&g_K[(((size_t)b * 8 + h) * 4096 + cs * CK_) * 16];
        const float4* V4 = (const float4*)&g_V[(((size_t)b * 8 + h) * 4096 + cs * CK_) * 16];
        float4* Kd = &sm.a.K4[0][0];
        float4* Vd = &sm.a.V4[0][0];
        for (int idx = t; idx < CK_ * 4; idx += 256) { Kd[idx] = K4[idx]; Vd[idx] = V4[idx]; }
    }
    __syncthreads();

    // ---- phase 3: pairwise online-softmax over 64-key sub-chunk ----
    const int qi  = t & 63;
    const int sub = t >> 6;
    float m = -1e30f, l = 0.f;
    float o[16];
#pragma unroll
    for (int d = 0; d < 16; d++) o[d] = 0.f;

    if (qi < s) {
        float q[16];
#pragma unroll
        for (int d = 0; d < 16; d++) q[d] = sm.a.q[qi][d] * 0.25f;

        const int j0 = sub * KSUB_;
#pragma unroll 4
        for (int jj = 0; jj < KSUB_ / 2; jj++) {
            const int j = j0 + jj * 2;
            float4 ka0 = sm.a.K4[j][0],   ka1 = sm.a.K4[j][1];
            float4 ka2 = sm.a.K4[j][2],   ka3 = sm.a.K4[j][3];
            float sa =
                (q[0]*ka0.x + q[4]*ka1.x + q[8]*ka2.x  + q[12]*ka3.x) +
                (q[1]*ka0.y + q[5]*ka1.y + q[9]*ka2.y  + q[13]*ka3.y) +
                (q[2]*ka0.z + q[6]*ka1.z + q[10]*ka2.z + q[14]*ka3.z) +
                (q[3]*ka0.w + q[7]*ka1.w + q[11]*ka2.w + q[15]*ka3.w);
            float4 kb0 = sm.a.K4[j+1][0], kb1 = sm.a.K4[j+1][1];
            float4 kb2 = sm.a.K4[j+1][2], kb3 = sm.a.K4[j+1][3];
            float sb =
                (q[0]*kb0.x + q[4]*kb1.x + q[8]*kb2.x  + q[12]*kb3.x) +
                (q[1]*kb0.y + q[5]*kb1.y + q[9]*kb2.y  + q[13]*kb3.y) +
                (q[2]*kb0.z + q[6]*kb1.z + q[10]*kb2.z + q[14]*kb3.z) +
                (q[3]*kb0.w + q[7]*kb1.w + q[11]*kb2.w + q[15]*kb3.w);

            float nm   = fmaxf(m, fmaxf(sa, sb));
            float corr = __expf(m - nm);
            float pa   = __expf(sa - nm);
            float pb   = __expf(sb - nm);
            m = nm;
            l = l * corr + (pa + pb);

            float4 va0 = sm.a.V4[j][0],   vb0 = sm.a.V4[j+1][0];
            float4 va1 = sm.a.V4[j][1],   vb1 = sm.a.V4[j+1][1];
            o[0]  = o[0] *corr + pa*va0.x + pb*vb0.x;
            o[1]  = o[1] *corr + pa*va0.y + pb*vb0.y;
            o[2]  = o[2] *corr + pa*va0.z + pb*vb0.z;
            o[3]  = o[3] *corr + pa*va0.w + pb*vb0.w;
            o[4]  = o[4] *corr + pa*va1.x + pb*vb1.x;
            o[5]  = o[5] *corr + pa*va1.y + pb*vb1.y;
            o[6]  = o[6] *corr + pa*va1.z + pb*vb1.z;
            o[7]  = o[7] *corr + pa*va1.w + pb*vb1.w;
            float4 va2 = sm.a.V4[j][2],   vb2 = sm.a.V4[j+1][2];
            float4 va3 = sm.a.V4[j][3],   vb3 = sm.a.V4[j+1][3];
            o[8]  = o[8] *corr + pa*va2.x + pb*vb2.x;
            o[9]  = o[9] *corr + pa*va2.y + pb*vb2.y;
            o[10] = o[10]*corr + pa*va2.z + pb*vb2.z;
            o[11] = o[11]*corr + pa*va2.w + pb*vb2.w;
            o[12] = o[12]*corr + pa*va3.x + pb*vb3.x;
            o[13] = o[13]*corr + pa*va3.y + pb*vb3.y;
            o[14] = o[14]*corr + pa*va3.z + pb*vb3.z;
            o[15] = o[15]*corr + pa*va3.w + pb*vb3.w;
        }
    }

    // ---- phase 4: merge the 4 sub-partials per query (smem, aliased) ----
    __syncthreads();                       // everyone done reading K/V
    MergeSm* mg = (MergeSm*)&sm.a.K4[0][0];
    if (qi < s) {
        mg->M[qi][sub] = m;
        mg->L[qi][sub] = l;
#pragma unroll
        for (int d = 0; d < 16; d++) mg->O[qi][sub * 17 + d] = o[d];
    }
    __syncthreads();
    if (t < s) {
        float M = -1e30f, L = 0.f;
        float O[16];
#pragma unroll
        for (int d = 0; d < 16; d++) O[d] = 0.f;
#pragma unroll
        for (int u = 0; u < SUB_; u++) {
            float mc = mg->M[t][u];
            float lc = mg->L[t][u];
            float nM = fmaxf(M, mc);
            float e0 = __expf(M - nM), e1 = __expf(mc - nM);
            L = L * e0 + lc * e1;
#pragma unroll
            for (int d = 0; d < 16; d++)
                O[d] = O[d] * e0 + mg->O[t][u * 17 + d] * e1;
            M = nM;
        }
        int pidx = ((b * 8 + h) * 16 + cs) * 64 + t;
        g_M[par][pidx] = M;
        g_L[par][pidx] = L;
        float4* dst = (float4*)&g_O[par][(size_t)pidx * 16];
        dst[0] = make_float4(O[0],  O[1],  O[2],  O[3]);
        dst[1] = make_float4(O[4],  O[5],  O[6],  O[7]);
        dst[2] = make_float4(O[8],  O[9],  O[10], O[11]);
        dst[3] = make_float4(O[12], O[13], O[14], O[15]);
    }
}

// ---------------- final combine for ring 126 -------------------------------
__global__ void combine_write(int r, const float* __restrict__ x,
                              float* __restrict__ feats_out) {
    const int b = blockIdx.y, qi = blockIdx.x, c = threadIdx.x;
    const int lo = max(0, r - 63);
    const int col = 63 * (lo + qi) + r;
    const int par = r & 1;
    const int hh = c >> 4, d = c & 15;
    int base = ((b * 8 + hh) * 16) * 64 + qi;
    float M = -1e30f, L = 0.f, O = 0.f;
#pragma unroll 4
    for (int ch = 0; ch < 16; ch++) {
        int pidx = base + ch * 64;
        float mc = g_M[par][pidx];
        float lc = g_L[par][pidx];
        float oc = g_O[par][(size_t)pidx * 16 + d];
        float nM = fmaxf(M, mc);
        float e0 = __expf(M - nM), e1 = __expf(mc - nM);
        L = L * e0 + lc * e1;
        O = O * e0 + oc * e1;
        M = nM;
    }
    feats_out[((size_t)(b * 128 + c)) * 4096 + col] =
        x[((size_t)(b * 128 + c)) * 4096 + col] + O / L;
}

// ---------------- epilogue 1 ------------------------------------------------
__global__ void epi1_kernel(const float* __restrict__ Wv0,
                            const float* __restrict__ Wk1,
                            const float* __restrict__ feats_out) {
    __shared__ float anc[128];
    __shared__ float k1raw[128];
    __shared__ float hs[8];
    const int b = blockIdx.x, t = threadIdx.x;
    anc[t] = feats_out[((size_t)(b * 128 + t)) * 4096 + 0];
    __syncthreads();
    float av = 0.f, kv = 0.f;
#pragma unroll 8
    for (int c = 0; c < 128; c++) {
        av += Wv0[t * 128 + c] * anc[c];
        kv += Wk1[t * 128 + c] * anc[c];
    }
    g_va[b * 128 + t] = av;
    k1raw[t] = kv;
    __syncthreads();
    if (t < 8) {
        float ss = 0.f;
#pragma unroll
        for (int d = 0; d < 16; d++) { float v = k1raw[t * 16 + d]; ss += v * v; }
        hs[t] = rsqrtf(ss + 1e-8f);
    }
    __syncthreads();
    g_k1[(b * 8 + (t >> 4)) * 16 + (t & 15)] = k1raw[t] * hs[t >> 4];
}

// ---------------- epilogue 2 ------------------------------------------------
__global__ void epi2_kernel(const float* __restrict__ x,
                            const float* __restrict__ Wq1,
                            float* __restrict__ scores_out) {
    __shared__ float WsT[64][132];
    __shared__ float sva[128];
    __shared__ float sred[8][32];
    const int b  = blockIdx.y;
    const int t  = threadIdx.x;
    const int tx = t & 31;
    const int ty = t >> 5;
    const int n  = blockIdx.x * 32 + tx;

    if (t < 128) sva[t] = g_va[b * 128 + t];

    float acc[16];
#pragma unroll
    for (int i = 0; i < 16; i++) acc[i] = 0.f;

    for (int half = 0; half < 2; half++) {
        __syncthreads();
        for (int idx = t; idx < 64 * 128; idx += 256) {
            int co = idx >> 6, c = idx & 63;
            WsT[c][co] = Wq1[co * 128 + half * 64 + c];
        }
        __syncthreads();
#pragma unroll 4
        for (int c = 0; c < 64; c++) {
            float qx = x[((size_t)(b * 128 + half * 64 + c)) * 4096 + n] + sva[half * 64 + c];
            const float4* wr = (const float4*)&WsT[c][ty * 16];
            float4 w0 = wr[0], w1 = wr[1], w2 = wr[2], w3 = wr[3];
            acc[0]  += w0.x * qx;  acc[1]  += w0.y * qx;
            acc[2]  += w0.z * qx;  acc[3]  += w0.w * qx;
            acc[4]  += w1.x * qx;  acc[5]  += w1.y * qx;
            acc[6]  += w1.z * qx;  acc[7]  += w1.w * qx;
            acc[8]  += w2.x * qx;  acc[9]  += w2.y * qx;
            acc[10] += w2.z * qx;  acc[11] += w2.w * qx;
            acc[12] += w3.x * qx;  acc[13] += w3.y * qx;
            acc[14] += w3.z * qx;  acc[15] += w3.w * qx;
        }
    }
    float qq = 0.f, dot = 0.f;
#pragma unroll
    for (int d = 0; d < 16; d++) {
        qq  += acc[d] * acc[d];
        dot += acc[d] * g_k1[(b * 8 + ty) * 16 + d];
    }
    float m = dot * rsqrtf(qq + 1e-8f);
    sred[ty][tx] = (m + 1.0f) * 0.5f;
    __syncthreads();
    if (ty == 0) {
        float sum = 0.f;
#pragma unroll
        for (int hh = 0; hh < 8; hh++) sum += sred[hh][tx];
        scores_out[(size_t)b * 4096 + n] = sum * 0.125f;
    }
}

// ---------------------------------------------------------------------------
extern "C" void kernel_launch(void* const* d_in, const int* in_sizes, int n_in,
                              void* d_out, int out_size) {
    const float* x   = (const float*)d_in[0];
    const float* Wq0 = (const float*)d_in[1];
    const float* Wk0 = (const float*)d_in[2];
    const float* Wv0 = (const float*)d_in[3];
    const float* Wq1 = (const float*)d_in[4];
    const float* Wk1 = (const float*)d_in[5];
    float* feats_out  = (float*)d_out;
    float* scores_out = feats_out + (size_t)B_ * C_ * F_;

    proj_kernel<<<dim3(128, 3, B_), 256>>>(x, Wq0, Wk0, Wv0);

    for (int r = 0; r < NR_; r++) {
        attn_partial<<<dim3(NS_, H_, B_), 256>>>(r, x, Wk0, Wv0, feats_out);
    }
    combine_write<<<dim3(1, B_), 128>>>(126, x, feats_out);

    epi1_kernel<<<B_, 128>>>(Wv0, Wk1, feats_out);
    epi2_kernel<<<dim3(128, B_), 256>>>(x, Wq1, scores_out);
}

// round 4
// speedup vs baseline: 2.1316x; 1.2382x over previous
#include <cuda_runtime.h>
#include <math.h>

#define B_ 4
#define C_ 128
#define H_ 8
#define DH_ 16
#define F_ 4096
#define NR_ 127
#define NS_ 16      // key-split chunks
#define CK_ 256     // keys per chunk
#define SUB_ 4      // sub-chunks per CTA
#define KSUB_ 64    // keys per sub-chunk
#define SMAX_ 64

typedef unsigned long long ull;

// ------------------------- packed f32x2 helpers ----------------------------
__device__ __forceinline__ ull pk2(float lo, float hi) {
    ull r; asm("mov.b64 %0, {%1, %2};" : "=l"(r) : "f"(lo), "f"(hi)); return r;
}
__device__ __forceinline__ void upk2(ull v, float& lo, float& hi) {
    asm("mov.b64 {%0, %1}, %2;" : "=f"(lo), "=f"(hi) : "l"(v));
}
__device__ __forceinline__ ull fma2(ull a, ull b, ull c) {
    ull d; asm("fma.rn.f32x2 %0, %1, %2, %3;" : "=l"(d) : "l"(a), "l"(b), "l"(c)); return d;
}
__device__ __forceinline__ ull add2(ull a, ull b) {
    ull d; asm("add.rn.f32x2 %0, %1, %2;" : "=l"(d) : "l"(a), "l"(b)); return d;
}
__device__ __forceinline__ float ex2(float x) {
    float y; asm("ex2.approx.ftz.f32 %0, %1;" : "=f"(y) : "f"(x)); return y;
}

// ----------------------------- scratch ------------------------------------
__device__ float g_Q[B_*H_*F_*DH_];                 // (b,h,n,d) 8 MB
__device__ float g_K[B_*H_*F_*DH_];
__device__ float g_V[B_*H_*F_*DH_];
__device__ float g_L[2][B_*H_*NS_*SMAX_];
__device__ float g_O[2][B_*H_*NS_*SMAX_*DH_];
__device__ float g_va[B_*C_];                       // Wv0 @ anchor
__device__ float g_k1[B_*H_*DH_];                   // normalized Wk1 @ anchor

// --------------------- prologue: Q/K/V = W @ x -----------------------------
// grid (F/32, 3, B), block 256 = 32 cols x 8 heads
__global__ void proj_kernel(const float* __restrict__ x,
                            const float* __restrict__ Wq,
                            const float* __restrict__ Wk,
                            const float* __restrict__ Wv) {
    __shared__ float WsT[64][132];
    const float* W   = (blockIdx.y == 0) ? Wq  : (blockIdx.y == 1 ? Wk  : Wv);
    float*       out = (blockIdx.y == 0) ? g_Q : (blockIdx.y == 1 ? g_K : g_V);
    const int b  = blockIdx.z;
    const int t  = threadIdx.x;
    const int tx = t & 31;
    const int ty = t >> 5;
    const int n  = blockIdx.x * 32 + tx;

    float acc[16];
#pragma unroll
    for (int i = 0; i < 16; i++) acc[i] = 0.f;

    for (int half = 0; half < 2; half++) {
        __syncthreads();
        for (int idx = t; idx < 64 * 128; idx += 256) {
            int co = idx >> 6, c = idx & 63;
            WsT[c][co] = W[co * 128 + half * 64 + c];
        }
        __syncthreads();
#pragma unroll 4
        for (int c = 0; c < 64; c++) {
            float xv = x[((size_t)(b * 128 + half * 64 + c)) * 4096 + n];
            const float4* wr = (const float4*)&WsT[c][ty * 16];
            float4 w0 = wr[0], w1 = wr[1], w2 = wr[2], w3 = wr[3];
            acc[0]  += w0.x * xv;  acc[1]  += w0.y * xv;
            acc[2]  += w0.z * xv;  acc[3]  += w0.w * xv;
            acc[4]  += w1.x * xv;  acc[5]  += w1.y * xv;
            acc[6]  += w1.z * xv;  acc[7]  += w1.w * xv;
            acc[8]  += w2.x * xv;  acc[9]  += w2.y * xv;
            acc[10] += w2.z * xv;  acc[11] += w2.w * xv;
            acc[12] += w3.x * xv;  acc[13] += w3.y * xv;
            acc[14] += w3.z * xv;  acc[15] += w3.w * xv;
        }
    }
    float4* dst = (float4*)&out[(((size_t)b * 8 + ty) * 4096 + n) * 16];
    dst[0] = make_float4(acc[0],  acc[1],  acc[2],  acc[3]);
    dst[1] = make_float4(acc[4],  acc[5],  acc[6],  acc[7]);
    dst[2] = make_float4(acc[8],  acc[9],  acc[10], acc[11]);
    dst[3] = make_float4(acc[12], acc[13], acc[14], acc[15]);
}

// ----------------- per-ring attention partial + lazy patch -----------------
struct PatchSm {
    float Wk[16][129];
    float Wv[16][129];
    float fc[5][129];
};
struct AttnSm {
    float4 K4[CK_][4];      // 16 KB
    float4 V4[CK_][4];      // 16 KB
    float  q[SMAX_][16];    // 4 KB
};
union SmU { PatchSm p; AttnSm a; };

// merge scratch aliased over K4/V4
struct MergeSm {
    float L[SMAX_][SUB_];
    float O[SMAX_][SUB_ * 17 + 1];
};

// grid (NS_, H_, B_), block 256
__global__ void __launch_bounds__(256, 4)
attn_partial(int r,
             const float* __restrict__ x,
             const float* __restrict__ Wk0,
             const float* __restrict__ Wv0,
             float* __restrict__ feats_out) {
    __shared__ SmU sm;
    const int cs = blockIdx.x, h = blockIdx.y, b = blockIdx.z;
    const int t = threadIdx.x;
    const int lo = max(0, r - 63), hi = min(r, 63), s = hi - lo + 1;
    const int par  = r & 1;
    const int par1 = par ^ 1;

    // ---- phase 1: combine ring r-1 partials (plain sums); patch K/V ----
    if (r > 0) {
        const int rm  = r - 1;
        const int lo1 = max(0, rm - 63), hi1 = min(rm, 63);
        int a = cs * 256 - rm;
        int imin = (a <= 0) ? lo1 : (a + 62) / 63;
        if (imin < lo1) imin = lo1;
        int imax = (cs * 256 + 255 - rm) / 63;
        if (imax > hi1) imax = hi1;
        const int np = imax - imin + 1;
        if (np > 0) {
            for (int idx = t; idx < 16 * 128; idx += 256) {
                int row = idx >> 7, c = idx & 127;
                sm.p.Wk[row][c] = Wk0[(h * 16 + row) * 128 + c];
                sm.p.Wv[row][c] = Wv0[(h * 16 + row) * 128 + c];
            }
            for (int idx = t; idx < np * 128; idx += 256) {
                int ci = idx >> 7, c = idx & 127;
                int hh = c >> 4, d = c & 15;
                int i  = imin + ci;
                int qi = i - lo1;
                int col = 63 * i + rm;
                int base = ((b * 8 + hh) * 16) * 64 + qi;
                float L = 0.f, O = 0.f;
#pragma unroll 4
                for (int ch = 0; ch < 16; ch++) {
                    int pidx = base + ch * 64;
                    L += g_L[par1][pidx];
                    O += g_O[par1][(size_t)pidx * 16 + d];
                }
                float f = x[((size_t)(b * 128 + c)) * 4096 + col] + O / L;
                sm.p.fc[ci][c] = f;
                if (h == 0)
                    feats_out[((size_t)(b * 128 + c)) * 4096 + col] = f;
            }
            __syncthreads();
            for (int w = t; w < np * 32; w += 256) {
                int which = w / (np * 16);          // 0->K, 1->V
                int m2 = w % (np * 16);
                int ci = m2 >> 4, row = m2 & 15;
                float accp = 0.f;
                if (which == 0) {
#pragma unroll 8
                    for (int c = 0; c < 128; c++) accp += sm.p.Wk[row][c] * sm.p.fc[ci][c];
                } else {
#pragma unroll 8
                    for (int c = 0; c < 128; c++) accp += sm.p.Wv[row][c] * sm.p.fc[ci][c];
                }
                int col = 63 * (imin + ci) + rm;
                float* dst = which ? g_V : g_K;
                dst[(((size_t)b * 8 + h) * 4096 + col) * 16 + row] = accp;
            }
        }
        __syncthreads();
    }

    // ---- phase 2: stage q, K-chunk, V-chunk into smem ----
    for (int idx = t; idx < s * 16; idx += 256) {
        int i = idx >> 4, d = idx & 15;
        int col = 63 * (lo + i) + r;
        sm.a.q[i][d] = g_Q[(((size_t)b * 8 + h) * 4096 + col) * 16 + d];
    }
    {
        const float4* K4 = (const float4*)&g_K[(((size_t)b * 8 + h) * 4096 + cs * CK_) * 16];
        const float4* V4 = (const float4*)&g_V[(((size_t)b * 8 + h) * 4096 + cs * CK_) * 16];
        float4* Kd = &sm.a.K4[0][0];
        float4* Vd = &sm.a.V4[0][0];
        for (int idx = t; idx < CK_ * 4; idx += 256) { Kd[idx] = K4[idx]; Vd[idx] = V4[idx]; }
    }
    __syncthreads();

    // ---- phase 3: fixed-max (m=0) softmax partial, packed f32x2 ----
    const int qi  = t & 63;
    const int sub = t >> 6;
    const ull Z = 0ull;                 // packed (0,0)
    ull o2[8];
#pragma unroll
    for (int i = 0; i < 8; i++) o2[i] = Z;
    float l = 0.f;

    if (qi < s) {
        const float CSC = 0.36067376022224085f;   // 0.25 * log2(e)
        ull q2[8];
#pragma unroll
        for (int i = 0; i < 8; i++)
            q2[i] = pk2(sm.a.q[qi][2*i] * CSC, sm.a.q[qi][2*i+1] * CSC);

        const int j0 = sub * KSUB_;
#pragma unroll 4
        for (int jj = 0; jj < KSUB_; jj++) {
            const int j = j0 + jj;
            const ulonglong2* Kp = (const ulonglong2*)&sm.a.K4[j][0];
            ulonglong2 k01 = Kp[0], k23 = Kp[1], k45 = Kp[2], k67 = Kp[3];
            ull a0 = fma2(q2[0], k01.x, Z);
            ull a1 = fma2(q2[1], k01.y, Z);
            a0 = fma2(q2[2], k23.x, a0);
            a1 = fma2(q2[3], k23.y, a1);
            a0 = fma2(q2[4], k45.x, a0);
            a1 = fma2(q2[5], k45.y, a1);
            a0 = fma2(q2[6], k67.x, a0);
            a1 = fma2(q2[7], k67.y, a1);
            ull as = add2(a0, a1);
            float slo, shi; upk2(as, slo, shi);
            float p = ex2(slo + shi);           // exp(score/4) in base-2 form
            l += p;
            ull p2 = pk2(p, p);
            const ulonglong2* Vp = (const ulonglong2*)&sm.a.V4[j][0];
            ulonglong2 v01 = Vp[0], v23 = Vp[1], v45 = Vp[2], v67 = Vp[3];
            o2[0] = fma2(p2, v01.x, o2[0]);
            o2[1] = fma2(p2, v01.y, o2[1]);
            o2[2] = fma2(p2, v23.x, o2[2]);
            o2[3] = fma2(p2, v23.y, o2[3]);
            o2[4] = fma2(p2, v45.x, o2[4]);
            o2[5] = fma2(p2, v45.y, o2[5]);
            o2[6] = fma2(p2, v67.x, o2[6]);
            o2[7] = fma2(p2, v67.y, o2[7]);
        }
    }

    // ---- phase 4: sum the 4 sub-partials per query (smem, aliased) ----
    __syncthreads();                       // everyone done reading K/V
    MergeSm* mg = (MergeSm*)&sm.a.K4[0][0];
    if (qi < s) {
        mg->L[qi][sub] = l;
#pragma unroll
        for (int i = 0; i < 8; i++) {
            float lo_, hi_; upk2(o2[i], lo_, hi_);
            mg->O[qi][sub * 17 + 2*i]     = lo_;
            mg->O[qi][sub * 17 + 2*i + 1] = hi_;
        }
    }
    __syncthreads();
    if (t < s) {
        float L = 0.f;
        float O[16];
#pragma unroll
        for (int d = 0; d < 16; d++) O[d] = 0.f;
#pragma unroll
        for (int u = 0; u < SUB_; u++) {
            L += mg->L[t][u];
#pragma unroll
            for (int d = 0; d < 16; d++)
                O[d] += mg->O[t][u * 17 + d];
        }
        int pidx = ((b * 8 + h) * 16 + cs) * 64 + t;
        g_L[par][pidx] = L;
        float4* dst = (float4*)&g_O[par][(size_t)pidx * 16];
        dst[0] = make_float4(O[0],  O[1],  O[2],  O[3]);
        dst[1] = make_float4(O[4],  O[5],  O[6],  O[7]);
        dst[2] = make_float4(O[8],  O[9],  O[10], O[11]);
        dst[3] = make_float4(O[12], O[13], O[14], O[15]);
    }
}

// ---------------- final combine for ring 126 -------------------------------
__global__ void combine_write(int r, const float* __restrict__ x,
                              float* __restrict__ feats_out) {
    const int b = blockIdx.y, qi = blockIdx.x, c = threadIdx.x;
    const int lo = max(0, r - 63);
    const int col = 63 * (lo + qi) + r;
    const int par = r & 1;
    const int hh = c >> 4, d = c & 15;
    int base = ((b * 8 + hh) * 16) * 64 + qi;
    float L = 0.f, O = 0.f;
#pragma unroll 4
    for (int ch = 0; ch < 16; ch++) {
        int pidx = base + ch * 64;
        L += g_L[par][pidx];
        O += g_O[par][(size_t)pidx * 16 + d];
    }
    feats_out[((size_t)(b * 128 + c)) * 4096 + col] =
        x[((size_t)(b * 128 + c)) * 4096 + col] + O / L;
}

// ---------------- epilogue 1 ------------------------------------------------
__global__ void epi1_kernel(const float* __restrict__ Wv0,
                            const float* __restrict__ Wk1,
                            const float* __restrict__ feats_out) {
    __shared__ float anc[128];
    __shared__ float k1raw[128];
    __shared__ float hs[8];
    const int b = blockIdx.x, t = threadIdx.x;
    anc[t] = feats_out[((size_t)(b * 128 + t)) * 4096 + 0];
    __syncthreads();
    float av = 0.f, kv = 0.f;
#pragma unroll 8
    for (int c = 0; c < 128; c++) {
        av += Wv0[t * 128 + c] * anc[c];
        kv += Wk1[t * 128 + c] * anc[c];
    }
    g_va[b * 128 + t] = av;
    k1raw[t] = kv;
    __syncthreads();
    if (t < 8) {
        float ss = 0.f;
#pragma unroll
        for (int d = 0; d < 16; d++) { float v = k1raw[t * 16 + d]; ss += v * v; }
        hs[t] = rsqrtf(ss + 1e-8f);
    }
    __syncthreads();
    g_k1[(b * 8 + (t >> 4)) * 16 + (t & 15)] = k1raw[t] * hs[t >> 4];
}

// ---------------- epilogue 2 ------------------------------------------------
__global__ void epi2_kernel(const float* __restrict__ x,
                            const float* __restrict__ Wq1,
                            float* __restrict__ scores_out) {
    __shared__ float WsT[64][132];
    __shared__ float sva[128];
    __shared__ float sred[8][32];
    const int b  = blockIdx.y;
    const int t  = threadIdx.x;
    const int tx = t & 31;
    const int ty = t >> 5;
    const int n  = blockIdx.x * 32 + tx;

    if (t < 128) sva[t] = g_va[b * 128 + t];

    float acc[16];
#pragma unroll
    for (int i = 0; i < 16; i++) acc[i] = 0.f;

    for (int half = 0; half < 2; half++) {
        __syncthreads();
        for (int idx = t; idx < 64 * 128; idx += 256) {
            int co = idx >> 6, c = idx & 63;
            WsT[c][co] = Wq1[co * 128 + half * 64 + c];
        }
        __syncthreads();
#pragma unroll 4
        for (int c = 0; c < 64; c++) {
            float qx = x[((size_t)(b * 128 + half * 64 + c)) * 4096 + n] + sva[half * 64 + c];
            const float4* wr = (const float4*)&WsT[c][ty * 16];
            float4 w0 = wr[0], w1 = wr[1], w2 = wr[2], w3 = wr[3];
            acc[0]  += w0.x * qx;  acc[1]  += w0.y * qx;
            acc[2]  += w0.z * qx;  acc[3]  += w0.w * qx;
            acc[4]  += w1.x * qx;  acc[5]  += w1.y * qx;
            acc[6]  += w1.z * qx;  acc[7]  += w1.w * qx;
            acc[8]  += w2.x * qx;  acc[9]  += w2.y * qx;
            acc[10] += w2.z * qx;  acc[11] += w2.w * qx;
            acc[12] += w3.x * qx;  acc[13] += w3.y * qx;
            acc[14] += w3.z * qx;  acc[15] += w3.w * qx;
        }
    }
    float qq = 0.f, dot = 0.f;
#pragma unroll
    for (int d = 0; d < 16; d++) {
        qq  += acc[d] * acc[d];
        dot += acc[d] * g_k1[(b * 8 + ty) * 16 + d];
    }
    float m = dot * rsqrtf(qq + 1e-8f);
    sred[ty][tx] = (m + 1.0f) * 0.5f;
    __syncthreads();
    if (ty == 0) {
        float sum = 0.f;
#pragma unroll
        for (int hh = 0; hh < 8; hh++) sum += sred[hh][tx];
        scores_out[(size_t)b * 4096 + n] = sum * 0.125f;
    }
}

// ---------------------------------------------------------------------------
extern "C" void kernel_launch(void* const* d_in, const int* in_sizes, int n_in,
                              void* d_out, int out_size) {
    const float* x   = (const float*)d_in[0];
    const float* Wq0 = (const float*)d_in[1];
    const float* Wk0 = (const float*)d_in[2];
    const float* Wv0 = (const float*)d_in[3];
    const float* Wq1 = (const float*)d_in[4];
    const float* Wk1 = (const float*)d_in[5];
    float* feats_out  = (float*)d_out;
    float* scores_out = feats_out + (size_t)B_ * C_ * F_;

    proj_kernel<<<dim3(128, 3, B_), 256>>>(x, Wq0, Wk0, Wv0);

    for (int r = 0; r < NR_; r++) {
        attn_partial<<<dim3(NS_, H_, B_), 256>>>(r, x, Wk0, Wv0, feats_out);
    }
    combine_write<<<dim3(1, B_), 128>>>(126, x, feats_out);

    epi1_kernel<<<B_, 128>>>(Wv0, Wk1, feats_out);
    epi2_kernel<<<dim3(128, B_), 256>>>(x, Wq1, scores_out);
}